// round 1
// baseline (speedup 1.0000x reference)
#include <cuda_runtime.h>
#include <math.h>

#define D      200
#define NE     40000
#define TOT    160000
#define EHALF  80000
#define R2     200
#define NB     1024
#define EPSV   1e-5f

// ---------------- scratch (static device globals; no allocation) ----------------
__device__ float g_deg[2 * NE];
__device__ float g_norm[TOT];
__device__ float g_rel[(R2 + 1) * D];     // concat(r, loop_rel) for current layer
__device__ float g_r1[R2 * D];            // r after layer 1
__device__ float g_r2[R2 * D];            // r after layer 2
__device__ float g_Q[(size_t)TOT * D];    // qualifier pre-matmul features
__device__ float g_P[(size_t)TOT * D];    // message pre-matmul features
__device__ float g_agg[NE * D];           // in+out+loop accumulator (pre-BN)
__device__ float g_x1[NE * D];            // x after layer 1
__device__ float g_sum[D], g_sumsq[D], g_cA[D], g_cB[D];

// ---------------- degree / norm ----------------
__global__ void degree_k(const int* __restrict__ ei, float* __restrict__ deg) {
    int i = blockIdx.x * blockDim.x + threadIdx.x;
    if (i < TOT) {
        int off = (i >= EHALF) ? NE : 0;
        atomicAdd(&deg[off + ei[i]], 1.0f);
    }
}

__global__ void norm_k(const int* __restrict__ ei, const float* __restrict__ deg,
                       float* __restrict__ nrm) {
    int i = blockIdx.x * blockDim.x + threadIdx.x;
    if (i < TOT) {
        int off = (i >= EHALF) ? NE : 0;
        float a = deg[off + ei[i]];
        float b = deg[off + ei[TOT + i]];
        float va = (a > 0.f) ? rsqrtf(a) : 0.f;
        float vb = (b > 0.f) ? rsqrtf(b) : 0.f;
        nrm[i] = va * vb;
    }
}

// ---------------- qualifier feature build: Q[e,f] = sum_q x[qe]*rel[qr] ----------------
__global__ void build_q_k(const float* __restrict__ x, const float* __restrict__ rel,
                          const int* __restrict__ qe, const int* __restrict__ qr,
                          float* __restrict__ Q) {
    int e = blockIdx.x;
    int f = threadIdx.x;
    int e0 = qe[e], e1 = qe[TOT + e];
    int r0 = qr[e], r1 = qr[TOT + e];
    if (f < D)
        Q[(size_t)e * D + f] = x[(size_t)e0 * D + f] * rel[r0 * D + f]
                             + x[(size_t)e1 * D + f] * rel[r1 * D + f];
}

// ---------------- tiled fp32 GEMM with fused epilogues ----------------
// MODE 0: C[gm] = acc                                  (rel update)
// MODE 1: P[gm] = x[src[gm]] * (0.5*rel[et[gm]] + 0.5*acc)   (qual -> P)
// MODE 2: atomicAdd(agg[dst[e]], acc * norm[e]), e = edgeBase+gm  (msg scatter)
// MODE 3: A scaled by colScale on load; atomicAdd(C[gm], acc)    (self-loop)
constexpr int BM = 64, BK = 25, BN = 200, NT = 256;

template <int MODE>
__global__ __launch_bounds__(NT)
void gemm_k(const float* __restrict__ A, const float* __restrict__ Bw,
            float* __restrict__ C, int M,
            const float* __restrict__ colScale,
            const int* __restrict__ ei, const int* __restrict__ et,
            const float* __restrict__ x, const float* __restrict__ rel,
            const float* __restrict__ normArr, int edgeBase) {
    __shared__ float As[BM][BK];
    __shared__ float Bs[BK][BN];
    const int t  = threadIdx.x;
    const int tx = t & 7;        // col base 0..7
    const int ty = t >> 3;       // row pair 0..31
    const int m0 = blockIdx.x * BM;

    float acc[2][25];
#pragma unroll
    for (int r = 0; r < 2; r++)
#pragma unroll
        for (int j = 0; j < 25; j++) acc[r][j] = 0.f;

    for (int k0 = 0; k0 < D; k0 += BK) {
        for (int i = t; i < BM * BK; i += NT) {
            int r = i / BK, kk = i - r * BK;
            int gm = m0 + r;
            float v = (gm < M) ? A[(size_t)gm * D + k0 + kk] : 0.f;
            if (MODE == 3) v *= colScale[k0 + kk];
            As[r][kk] = v;
        }
        for (int i = t; i < BK * BN; i += NT) {
            int kk = i / BN, c = i - kk * BN;
            Bs[kk][c] = Bw[(k0 + kk) * D + c];
        }
        __syncthreads();
#pragma unroll
        for (int kk = 0; kk < BK; kk++) {
            float a0 = As[ty * 2][kk];
            float a1 = As[ty * 2 + 1][kk];
#pragma unroll
            for (int j = 0; j < 25; j++) {
                float b = Bs[kk][tx + 8 * j];
                acc[0][j] += a0 * b;
                acc[1][j] += a1 * b;
            }
        }
        __syncthreads();
    }

#pragma unroll
    for (int rr = 0; rr < 2; rr++) {
        int gm = m0 + ty * 2 + rr;
        if (gm >= M) continue;
        if (MODE == 0) {
#pragma unroll
            for (int j = 0; j < 25; j++) C[(size_t)gm * D + tx + 8 * j] = acc[rr][j];
        } else if (MODE == 1) {
            int s  = ei[gm];
            int ev = et[gm];
            const float* xr = x + (size_t)s * D;
            const float* rv = rel + ev * D;
#pragma unroll
            for (int j = 0; j < 25; j++) {
                int f = tx + 8 * j;
                C[(size_t)gm * D + f] = xr[f] * (0.5f * rv[f] + 0.5f * acc[rr][j]);
            }
        } else if (MODE == 2) {
            int e = edgeBase + gm;
            int dd = ei[TOT + e];
            float nm = normArr[e];
            float* cp = C + (size_t)dd * D;
#pragma unroll
            for (int j = 0; j < 25; j++) atomicAdd(&cp[tx + 8 * j], acc[rr][j] * nm);
        } else {
            float* cp = C + (size_t)gm * D;
#pragma unroll
            for (int j = 0; j < 25; j++) atomicAdd(&cp[tx + 8 * j], acc[rr][j]);
        }
    }
}

// ---------------- BatchNorm (train-stats) + tanh, with bias/scale folding ----------------
__global__ void bn_stats_k(const float* __restrict__ t, float* __restrict__ sum,
                           float* __restrict__ sumsq) {
    int f = threadIdx.x;
    if (f >= D) return;
    int r0 = blockIdx.x * 250;
    float s = 0.f, ss = 0.f;
    for (int r = r0; r < r0 + 250; r++) {
        float v = t[(size_t)r * D + f];
        s += v; ss += v * v;
    }
    atomicAdd(&sum[f], s);
    atomicAdd(&sumsq[f], ss);
}

__global__ void bn_final_k(const float* __restrict__ sum, const float* __restrict__ sumsq,
                           const float* __restrict__ gamma, const float* __restrict__ beta,
                           float* __restrict__ cA, float* __restrict__ cB) {
    int f = threadIdx.x;
    if (f >= D) return;
    float mean = sum[f] * (1.f / NE);          // mean of t (pre /3, pre bias)
    float var  = sumsq[f] * (1.f / NE) - mean * mean;
    if (var < 0.f) var = 0.f;
    // out = t/3 + bias; BN removes bias; var_out = var_t/9
    float rs = rsqrtf(var * (1.f / 9.f) + EPSV);
    float a  = gamma[f] * rs * (1.f / 3.f);
    cA[f] = a;
    cB[f] = beta[f] - a * mean;
}

__global__ void bn_apply_k(const float* __restrict__ t, const float* __restrict__ cA,
                           const float* __restrict__ cB, float* __restrict__ xo) {
    int i = blockIdx.x * blockDim.x + threadIdx.x;
    if (i < NE * D) {
        int f = i % D;
        xo[i] = tanhf(cA[f] * t[i] + cB[f]);
    }
}

// ---------------- output gathers ----------------
__global__ void gather_k(const float* __restrict__ src, const int* __restrict__ idx,
                         float* __restrict__ out) {
    int b = blockIdx.x;
    int f = threadIdx.x;
    if (f < D) out[(size_t)b * D + f] = src[(size_t)idx[b] * D + f];
}

// ---------------- driver ----------------
extern "C" void kernel_launch(void* const* d_in, const int* in_sizes, int n_in,
                              void* d_out, int out_size) {
    const int* ei  = (const int*)d_in[0];
    const int* et  = (const int*)d_in[1];
    const int* qe  = (const int*)d_in[2];
    const int* qr  = (const int*)d_in[3];
    const int* sub = (const int*)d_in[4];
    const int* rel = (const int*)d_in[5];
    const float* init_embed = (const float*)d_in[6];
    const float* init_rel   = (const float*)d_in[7];
    // per-layer params: w_loop, w_in, w_out, w_rel, w_q, loop_rel, bias, gamma, beta
    const float* L[2][9];
    for (int l = 0; l < 2; l++)
        for (int p = 0; p < 9; p++) L[l][p] = (const float*)d_in[8 + l * 9 + p];

    float *deg, *nrm, *relbuf, *r1, *r2, *Q, *P, *agg, *x1, *sum, *sumsq, *cA, *cB;
    cudaGetSymbolAddress((void**)&deg,    g_deg);
    cudaGetSymbolAddress((void**)&nrm,    g_norm);
    cudaGetSymbolAddress((void**)&relbuf, g_rel);
    cudaGetSymbolAddress((void**)&r1,     g_r1);
    cudaGetSymbolAddress((void**)&r2,     g_r2);
    cudaGetSymbolAddress((void**)&Q,      g_Q);
    cudaGetSymbolAddress((void**)&P,      g_P);
    cudaGetSymbolAddress((void**)&agg,    g_agg);
    cudaGetSymbolAddress((void**)&x1,     g_x1);
    cudaGetSymbolAddress((void**)&sum,    g_sum);
    cudaGetSymbolAddress((void**)&sumsq,  g_sumsq);
    cudaGetSymbolAddress((void**)&cA,     g_cA);
    cudaGetSymbolAddress((void**)&cB,     g_cB);

    float* out     = (float*)d_out;
    float* out_sub = out;
    float* out_rel = out + NB * D;
    float* out_x   = out + 2 * NB * D;

    // degrees / norms (layer-invariant)
    cudaMemsetAsync(deg, 0, 2 * NE * sizeof(float));
    degree_k<<<(TOT + 255) / 256, 256>>>(ei, deg);
    norm_k<<<(TOT + 255) / 256, 256>>>(ei, deg, nrm);

    for (int l = 0; l < 2; l++) {
        const float* x_in = l ? x1 : init_embed;
        const float* r_in = l ? r1 : init_rel;
        float* x_out = l ? out_x : x1;
        float* r_out = l ? r2 : r1;

        // rel_embed = concat(r_in, loop_rel)
        cudaMemcpyAsync(relbuf, r_in, R2 * D * sizeof(float), cudaMemcpyDeviceToDevice);
        cudaMemcpyAsync(relbuf + R2 * D, L[l][5], D * sizeof(float), cudaMemcpyDeviceToDevice);
        cudaMemsetAsync(agg, 0, (size_t)NE * D * sizeof(float));
        cudaMemsetAsync(sum, 0, D * sizeof(float));
        cudaMemsetAsync(sumsq, 0, D * sizeof(float));

        // Q build (both sides at once)
        build_q_k<<<TOT, 224>>>(x_in, relbuf, qe, qr, Q);
        // qual GEMM + fused P construction
        gemm_k<1><<<TOT / BM, NT>>>(Q, L[l][4], P, TOT, nullptr, ei, et, x_in, relbuf,
                                    nullptr, 0);
        // msg GEMMs + fused norm-scaled scatter (in side then out side)
        gemm_k<2><<<EHALF / BM, NT>>>(P, L[l][1], agg, EHALF, nullptr, ei, nullptr,
                                      nullptr, nullptr, nrm, 0);
        gemm_k<2><<<EHALF / BM, NT>>>(P + (size_t)EHALF * D, L[l][2], agg, EHALF, nullptr,
                                      ei, nullptr, nullptr, nullptr, nrm, EHALF);
        // self-loop GEMM: (x * loop_rel) @ w_loop accumulated into agg
        gemm_k<3><<<NE / BM, NT>>>(x_in, L[l][0], agg, NE, relbuf + R2 * D, nullptr,
                                   nullptr, nullptr, nullptr, nullptr, 0);
        // BN + tanh
        bn_stats_k<<<NE / 250, 224>>>(agg, sum, sumsq);
        bn_final_k<<<1, 224>>>(sum, sumsq, L[l][7], L[l][8], cA, cB);
        bn_apply_k<<<(NE * D + 255) / 256, 256>>>(agg, cA, cB, x_out);
        // rel update: (r_in @ w_rel)  (loop row dropped by [:-1])
        gemm_k<0><<<(R2 + BM - 1) / BM, NT>>>(r_in, L[l][3], r_out, R2, nullptr, nullptr,
                                              nullptr, nullptr, nullptr, nullptr, 0);
    }

    gather_k<<<NB, 224>>>(out_x, sub, out_sub);
    gather_k<<<NB, 224>>>(r2, rel, out_rel);
}

// round 2
// speedup vs baseline: 1.2428x; 1.2428x over previous
#include <cuda_runtime.h>
#include <math.h>

#define D      200
#define NE     40000
#define TOT    160000
#define EHALF  80000
#define R2     200
#define NB     1024
#define EPSV   1e-5f

// ---------------- scratch (static device globals; no allocation) ----------------
__device__ float g_deg[2 * NE];
__device__ float g_norm[TOT];
__device__ float g_rel[(R2 + 1) * D];
__device__ float g_r1[R2 * D];
__device__ float g_r2[R2 * D];
__device__ float g_Q[(size_t)TOT * D];
__device__ float g_P[(size_t)TOT * D];
__device__ float g_agg[NE * D];
__device__ float g_x1[NE * D];
__device__ float g_sum[D], g_sumsq[D], g_cA[D], g_cB[D];

// packed f32x2 FMA (sm_103a FFMA2 — only reachable via PTX)
__device__ __forceinline__ void fma2(float2& c, const float2& a, const float2& b) {
    unsigned long long cc = *reinterpret_cast<const unsigned long long*>(&c);
    unsigned long long aa = *reinterpret_cast<const unsigned long long*>(&a);
    unsigned long long bb = *reinterpret_cast<const unsigned long long*>(&b);
    asm("fma.rn.f32x2 %0, %1, %2, %0;" : "+l"(cc) : "l"(aa), "l"(bb));
    c = *reinterpret_cast<float2*>(&cc);
}

// ---------------- degree / norm ----------------
__global__ void degree_k(const int* __restrict__ ei, float* __restrict__ deg) {
    int i = blockIdx.x * blockDim.x + threadIdx.x;
    if (i < TOT) {
        int off = (i >= EHALF) ? NE : 0;
        atomicAdd(&deg[off + ei[i]], 1.0f);
    }
}

__global__ void norm_k(const int* __restrict__ ei, const float* __restrict__ deg,
                       float* __restrict__ nrm) {
    int i = blockIdx.x * blockDim.x + threadIdx.x;
    if (i < TOT) {
        int off = (i >= EHALF) ? NE : 0;
        float a = deg[off + ei[i]];
        float b = deg[off + ei[TOT + i]];
        float va = (a > 0.f) ? rsqrtf(a) : 0.f;
        float vb = (b > 0.f) ? rsqrtf(b) : 0.f;
        nrm[i] = va * vb;
    }
}

// ---------------- qualifier feature build ----------------
__global__ void build_q_k(const float* __restrict__ x, const float* __restrict__ rel,
                          const int* __restrict__ qe, const int* __restrict__ qr,
                          float* __restrict__ Q) {
    int e = blockIdx.x;
    int f = threadIdx.x;
    int e0 = qe[e], e1 = qe[TOT + e];
    int r0 = qr[e], r1 = qr[TOT + e];
    if (f < D)
        Q[(size_t)e * D + f] = x[(size_t)e0 * D + f] * rel[r0 * D + f]
                             + x[(size_t)e1 * D + f] * rel[r1 * D + f];
}

// ---------------- FFMA2 tiled GEMM with fused epilogues ----------------
// MODE 0: C[gm] = acc                                   (rel update)
// MODE 1: P[gm] = x[src[gm]] * (0.5*rel[et[gm]] + 0.5*acc)
// MODE 2: atomicAdd(agg[dst[e]], acc * norm[e]); both halves in one grid
// MODE 3: A scaled by colScale on load; atomicAdd(C[gm], acc)
constexpr int BM = 128, BK = 20, BN = 200, NT = 256;
constexpr int BLKS_HALF = EHALF / BM;   // 625

template <int MODE>
__global__ __launch_bounds__(NT)
void gemm_k(const float* __restrict__ A, const float* __restrict__ Bw,
            const float* __restrict__ Bw2,
            float* __restrict__ C, int M,
            const float* __restrict__ colScale,
            const int* __restrict__ ei, const int* __restrict__ et,
            const float* __restrict__ x, const float* __restrict__ rel,
            const float* __restrict__ normArr) {
    __shared__ float  Ast[BK][BM + 2];   // transposed A tile (padded)
    __shared__ float2 Bsd[BK][BN];       // B tile pre-duplicated {b,b}

    const int t  = threadIdx.x;
    const int tx = t & 7;                // col group 0..7
    const int ty = t >> 3;               // row quad 0..31

    const float* Ause = A;
    const float* Buse = Bw;
    int m0, ebase = 0;
    if (MODE == 2 && blockIdx.x >= BLKS_HALF) {
        Ause = A + (size_t)EHALF * D;
        Buse = Bw2;
        ebase = EHALF;
        m0 = (blockIdx.x - BLKS_HALF) * BM;
    } else {
        m0 = blockIdx.x * BM;
    }

    float2 acc01[25], acc23[25];
#pragma unroll
    for (int j = 0; j < 25; j++) {
        acc01[j] = make_float2(0.f, 0.f);
        acc23[j] = make_float2(0.f, 0.f);
    }

    for (int k0 = 0; k0 < D; k0 += BK) {
        // A tile -> transposed smem
        for (int i = t; i < BM * BK; i += NT) {
            int r = i / BK, kk = i - r * BK;
            int gm = m0 + r;
            float v = (gm < M) ? Ause[(size_t)gm * D + k0 + kk] : 0.f;
            if (MODE == 3) v *= colScale[k0 + kk];
            Ast[kk][r] = v;
        }
        // B tile -> duplicated smem
        for (int i = t; i < BK * BN; i += NT) {
            int kk = i / BN, c = i - kk * BN;
            float b = Buse[(k0 + kk) * D + c];
            Bsd[kk][c] = make_float2(b, b);
        }
        __syncthreads();
#pragma unroll 2
        for (int kk = 0; kk < BK; kk++) {
            float2 a01 = *reinterpret_cast<const float2*>(&Ast[kk][ty * 4]);
            float2 a23 = *reinterpret_cast<const float2*>(&Ast[kk][ty * 4 + 2]);
#pragma unroll
            for (int j = 0; j < 25; j++) {
                float2 b2 = Bsd[kk][tx + 8 * j];
                fma2(acc01[j], a01, b2);
                fma2(acc23[j], a23, b2);
            }
        }
        __syncthreads();
    }

#pragma unroll
    for (int rr = 0; rr < 4; rr++) {
        int gm = m0 + ty * 4 + rr;
        if (gm >= M) continue;
        if (MODE == 0) {
#pragma unroll
            for (int j = 0; j < 25; j++) {
                float v = (rr < 2) ? (rr == 0 ? acc01[j].x : acc01[j].y)
                                   : (rr == 2 ? acc23[j].x : acc23[j].y);
                C[(size_t)gm * D + tx + 8 * j] = v;
            }
        } else if (MODE == 1) {
            int s  = ei[gm];
            int ev = et[gm];
            const float* xr = x + (size_t)s * D;
            const float* rv = rel + ev * D;
#pragma unroll
            for (int j = 0; j < 25; j++) {
                float v = (rr < 2) ? (rr == 0 ? acc01[j].x : acc01[j].y)
                                   : (rr == 2 ? acc23[j].x : acc23[j].y);
                int f = tx + 8 * j;
                C[(size_t)gm * D + f] = xr[f] * (0.5f * rv[f] + 0.5f * v);
            }
        } else if (MODE == 2) {
            int e = ebase + gm;
            int dd = ei[TOT + e];
            float nm = normArr[e];
            float* cp = C + (size_t)dd * D;
#pragma unroll
            for (int j = 0; j < 25; j++) {
                float v = (rr < 2) ? (rr == 0 ? acc01[j].x : acc01[j].y)
                                   : (rr == 2 ? acc23[j].x : acc23[j].y);
                atomicAdd(&cp[tx + 8 * j], v * nm);
            }
        } else {
            float* cp = C + (size_t)gm * D;
#pragma unroll
            for (int j = 0; j < 25; j++) {
                float v = (rr < 2) ? (rr == 0 ? acc01[j].x : acc01[j].y)
                                   : (rr == 2 ? acc23[j].x : acc23[j].y);
                atomicAdd(&cp[tx + 8 * j], v);
            }
        }
    }
}

// ---------------- BatchNorm (train-stats) + tanh, bias/scale folded ----------------
__global__ void bn_stats_k(const float* __restrict__ t, float* __restrict__ sum,
                           float* __restrict__ sumsq) {
    int f = threadIdx.x;
    if (f >= D) return;
    int r0 = blockIdx.x * 250;
    float s = 0.f, ss = 0.f;
    for (int r = r0; r < r0 + 250; r++) {
        float v = t[(size_t)r * D + f];
        s += v; ss += v * v;
    }
    atomicAdd(&sum[f], s);
    atomicAdd(&sumsq[f], ss);
}

__global__ void bn_final_k(const float* __restrict__ sum, const float* __restrict__ sumsq,
                           const float* __restrict__ gamma, const float* __restrict__ beta,
                           float* __restrict__ cA, float* __restrict__ cB) {
    int f = threadIdx.x;
    if (f >= D) return;
    float mean = sum[f] * (1.f / NE);
    float var  = sumsq[f] * (1.f / NE) - mean * mean;
    if (var < 0.f) var = 0.f;
    float rs = rsqrtf(var * (1.f / 9.f) + EPSV);
    float a  = gamma[f] * rs * (1.f / 3.f);
    cA[f] = a;
    cB[f] = beta[f] - a * mean;
}

__global__ void bn_apply_k(const float* __restrict__ t, const float* __restrict__ cA,
                           const float* __restrict__ cB, float* __restrict__ xo) {
    int i = blockIdx.x * blockDim.x + threadIdx.x;
    if (i < NE * D) {
        int f = i % D;
        xo[i] = tanhf(cA[f] * t[i] + cB[f]);
    }
}

// ---------------- output gathers ----------------
__global__ void gather_k(const float* __restrict__ src, const int* __restrict__ idx,
                         float* __restrict__ out) {
    int b = blockIdx.x;
    int f = threadIdx.x;
    if (f < D) out[(size_t)b * D + f] = src[(size_t)idx[b] * D + f];
}

// ---------------- driver ----------------
extern "C" void kernel_launch(void* const* d_in, const int* in_sizes, int n_in,
                              void* d_out, int out_size) {
    const int* ei  = (const int*)d_in[0];
    const int* et  = (const int*)d_in[1];
    const int* qe  = (const int*)d_in[2];
    const int* qr  = (const int*)d_in[3];
    const int* sub = (const int*)d_in[4];
    const int* rel = (const int*)d_in[5];
    const float* init_embed = (const float*)d_in[6];
    const float* init_rel   = (const float*)d_in[7];
    const float* L[2][9];
    for (int l = 0; l < 2; l++)
        for (int p = 0; p < 9; p++) L[l][p] = (const float*)d_in[8 + l * 9 + p];

    float *deg, *nrm, *relbuf, *r1, *r2, *Q, *P, *agg, *x1, *sum, *sumsq, *cA, *cB;
    cudaGetSymbolAddress((void**)&deg,    g_deg);
    cudaGetSymbolAddress((void**)&nrm,    g_norm);
    cudaGetSymbolAddress((void**)&relbuf, g_rel);
    cudaGetSymbolAddress((void**)&r1,     g_r1);
    cudaGetSymbolAddress((void**)&r2,     g_r2);
    cudaGetSymbolAddress((void**)&Q,      g_Q);
    cudaGetSymbolAddress((void**)&P,      g_P);
    cudaGetSymbolAddress((void**)&agg,    g_agg);
    cudaGetSymbolAddress((void**)&x1,     g_x1);
    cudaGetSymbolAddress((void**)&sum,    g_sum);
    cudaGetSymbolAddress((void**)&sumsq,  g_sumsq);
    cudaGetSymbolAddress((void**)&cA,     g_cA);
    cudaGetSymbolAddress((void**)&cB,     g_cB);

    float* out     = (float*)d_out;
    float* out_sub = out;
    float* out_rel = out + NB * D;
    float* out_x   = out + 2 * NB * D;

    cudaMemsetAsync(deg, 0, 2 * NE * sizeof(float));
    degree_k<<<(TOT + 255) / 256, 256>>>(ei, deg);
    norm_k<<<(TOT + 255) / 256, 256>>>(ei, deg, nrm);

    for (int l = 0; l < 2; l++) {
        const float* x_in = l ? x1 : init_embed;
        const float* r_in = l ? r1 : init_rel;
        float* x_out = l ? out_x : x1;
        float* r_out = l ? r2 : r1;

        cudaMemcpyAsync(relbuf, r_in, R2 * D * sizeof(float), cudaMemcpyDeviceToDevice);
        cudaMemcpyAsync(relbuf + R2 * D, L[l][5], D * sizeof(float), cudaMemcpyDeviceToDevice);
        cudaMemsetAsync(agg, 0, (size_t)NE * D * sizeof(float));
        cudaMemsetAsync(sum, 0, D * sizeof(float));
        cudaMemsetAsync(sumsq, 0, D * sizeof(float));

        build_q_k<<<TOT, 224>>>(x_in, relbuf, qe, qr, Q);
        // qual GEMM + fused P construction
        gemm_k<1><<<TOT / BM, NT>>>(Q, L[l][4], nullptr, P, TOT, nullptr, ei, et,
                                    x_in, relbuf, nullptr);
        // both msg GEMMs in one grid + fused norm-scaled scatter
        gemm_k<2><<<2 * BLKS_HALF, NT>>>(P, L[l][1], L[l][2], agg, EHALF, nullptr,
                                         ei, nullptr, nullptr, nullptr, nrm);
        // self-loop GEMM
        gemm_k<3><<<(NE + BM - 1) / BM, NT>>>(x_in, L[l][0], nullptr, agg, NE,
                                              relbuf + R2 * D, nullptr, nullptr,
                                              nullptr, nullptr, nullptr);
        // BN + tanh
        bn_stats_k<<<NE / 250, 224>>>(agg, sum, sumsq);
        bn_final_k<<<1, 224>>>(sum, sumsq, L[l][7], L[l][8], cA, cB);
        bn_apply_k<<<(NE * D + 255) / 256, 256>>>(agg, cA, cB, x_out);
        // rel update
        gemm_k<0><<<(R2 + BM - 1) / BM, NT>>>(r_in, L[l][3], nullptr, r_out, R2,
                                              nullptr, nullptr, nullptr, nullptr,
                                              nullptr, nullptr);
    }

    gather_k<<<NB, 224>>>(out_x, sub, out_sub);
    gather_k<<<NB, 224>>>(r2, rel, out_rel);
}

// round 3
// speedup vs baseline: 1.3816x; 1.1117x over previous
#include <cuda_runtime.h>
#include <math.h>
#include <stdint.h>

#define D      200
#define NE     40000
#define TOT    160000
#define EHALF  80000
#define R2     200
#define NB     1024
#define EPSV   1e-5f

// ---------------- scratch (static device globals; no allocation) ----------------
__device__ float g_deg[2 * NE];
__device__ float g_norm[TOT];
__device__ int   g_cnt[NE];
__device__ int   g_off[NE + 1];
__device__ int   g_cur[NE];
__device__ int   g_ce[TOT];
__device__ float g_relbuf[(R2 + 1) * D];
__device__ float g_r1[R2 * D];
__device__ float g_r2[R2 * D];
__device__ float g_W2[D * D];
__device__ float g_Q[(size_t)TOT * D];
__device__ float g_P[(size_t)TOT * D];
__device__ float g_agg[NE * D];
__device__ float g_x1[NE * D];
__device__ float g_sum[D], g_sumsq[D], g_cA[D], g_cB[D];

// packed f32x2 FMA (sm_103a FFMA2 — PTX only)
__device__ __forceinline__ void fma2(float2& c, float2 a, float2 b) {
    unsigned long long cc = *reinterpret_cast<const unsigned long long*>(&c);
    unsigned long long aa = *reinterpret_cast<const unsigned long long*>(&a);
    unsigned long long bb = *reinterpret_cast<const unsigned long long*>(&b);
    asm("fma.rn.f32x2 %0, %1, %2, %0;" : "+l"(cc) : "l"(aa), "l"(bb));
    c = *reinterpret_cast<float2*>(&cc);
}

// ---------------- degree (norm) + dst count (CSR), norms ----------------
__global__ void degcnt_k(const int* __restrict__ ei, float* __restrict__ deg,
                         int* __restrict__ cnt) {
    int i = blockIdx.x * blockDim.x + threadIdx.x;
    if (i < TOT) {
        int off = (i >= EHALF) ? NE : 0;
        atomicAdd(&deg[off + ei[i]], 1.0f);
        atomicAdd(&cnt[ei[TOT + i]], 1);
    }
}

__global__ void norm_k(const int* __restrict__ ei, const float* __restrict__ deg,
                       float* __restrict__ nrm) {
    int i = blockIdx.x * blockDim.x + threadIdx.x;
    if (i < TOT) {
        int off = (i >= EHALF) ? NE : 0;
        float a = deg[off + ei[i]];
        float b = deg[off + ei[TOT + i]];
        float va = (a > 0.f) ? rsqrtf(a) : 0.f;
        float vb = (b > 0.f) ? rsqrtf(b) : 0.f;
        nrm[i] = va * vb;
    }
}

// ---------------- CSR build: scan + fill ----------------
#define SCAN_T 1024
__global__ void scan_k(const int* __restrict__ cnt, int* __restrict__ off,
                       int* __restrict__ cur) {
    __shared__ int part[SCAN_T];
    int t = threadIdx.x;
    const int CH = (NE + SCAN_T - 1) / SCAN_T;   // 40
    int base = t * CH;
    int s = 0;
    for (int i = 0; i < CH; i++) {
        int idx = base + i;
        if (idx < NE) s += cnt[idx];
    }
    part[t] = s;
    __syncthreads();
    for (int d = 1; d < SCAN_T; d <<= 1) {
        int v = (t >= d) ? part[t - d] : 0;
        __syncthreads();
        part[t] += v;
        __syncthreads();
    }
    int run = (t > 0) ? part[t - 1] : 0;   // exclusive prefix of this chunk
    for (int i = 0; i < CH; i++) {
        int idx = base + i;
        if (idx < NE) {
            off[idx] = run;
            cur[idx] = run;
            run += cnt[idx];
        }
    }
    if (t == SCAN_T - 1) off[NE] = TOT;
}

__global__ void fill_k(const int* __restrict__ ei, int* __restrict__ cur,
                       int* __restrict__ ce) {
    int e = blockIdx.x * blockDim.x + threadIdx.x;
    if (e < TOT) {
        int dst = ei[TOT + e];
        int pos = atomicAdd(&cur[dst], 1);
        ce[pos] = e;
    }
}

// ---------------- W2 = diag(loop_rel) @ w_loop ----------------
__global__ void prepw2_k(const float* __restrict__ wl, const float* __restrict__ lr,
                         float* __restrict__ W2) {
    int i = blockIdx.x * blockDim.x + threadIdx.x;
    if (i < D * D) {
        int k = i / D;
        W2[i] = lr[k] * wl[i];
    }
}

// ---------------- qualifier feature build (float2) ----------------
__global__ void build_q_k(const float* __restrict__ x, const float* __restrict__ rel,
                          const int* __restrict__ qe, const int* __restrict__ qr,
                          float* __restrict__ Q) {
    int e = blockIdx.x;
    int f = threadIdx.x;
    if (f >= D / 2) return;
    int e0 = qe[e], e1 = qe[TOT + e];
    int r0 = qr[e], r1 = qr[TOT + e];
    const float2* x0 = (const float2*)(x + (size_t)e0 * D);
    const float2* x1 = (const float2*)(x + (size_t)e1 * D);
    const float2* rl0 = (const float2*)(rel + (size_t)r0 * D);
    const float2* rl1 = (const float2*)(rel + (size_t)r1 * D);
    float2 a = x0[f], b = rl0[f], c = x1[f], d = rl1[f];
    float2 o;
    o.x = a.x * b.x + c.x * d.x;
    o.y = a.y * b.y + c.y * d.y;
    ((float2*)(Q + (size_t)e * D))[f] = o;
}

// ---------------- cp.async pipelined FFMA2 GEMM, fused epilogues ----------------
// MODE 0: C[gm] = acc                               (rel update; loop GEMM -> agg)
// MODE 1: P[gm] = x[src[gm]] * (0.5*rel[et[gm]] + 0.5*acc)
// MODE 2: P[e]  = acc * norm[e]  IN-PLACE (A==C==P); both halves one grid
constexpr int BM = 128, BK = 10, NT = 256, NSTG = 3, NIT = D / BK;  // 20 iters
constexpr int BLKS_HALF = EHALF / BM;  // 625

template <int MODE>
__global__ __launch_bounds__(NT, 2)
void gemm_k(const float* A, const float* __restrict__ Bw, const float* __restrict__ Bw2,
            float* C, int M,
            const int* __restrict__ ei, const int* __restrict__ et,
            const float* __restrict__ x, const float* __restrict__ rel,
            const float* __restrict__ normArr) {
    __shared__ __align__(16) float As[NSTG][BM * BK];
    __shared__ __align__(16) float Bs[NSTG][BK * D];

    const int t  = threadIdx.x;
    const int tx = t & 3;        // float2-col group 0..3
    const int ty = t >> 2;       // row pair 0..63

    const float* Ause = A;
    const float* Buse = Bw;
    int m0, ebase = 0;
    if (MODE == 2 && blockIdx.x >= BLKS_HALF) {
        ebase = EHALF;
        Ause = A + (size_t)EHALF * D;
        Buse = Bw2;
        m0 = (blockIdx.x - BLKS_HALF) * BM;
    } else {
        m0 = blockIdx.x * BM;
    }

    uint32_t sA = (uint32_t)__cvta_generic_to_shared(&As[0][0]);
    uint32_t sB = (uint32_t)__cvta_generic_to_shared(&Bs[0][0]);

    auto issue_tile = [&](int tile) {
        int s = tile % NSTG, k0 = tile * BK;
        for (int i = t; i < BM * BK / 2; i += NT) {     // 640 8B chunks
            int r = i / 5, cc = i - r * 5;
            int gm = m0 + r;
            const float* src = Ause + (size_t)gm * D + k0 + cc * 2;
            int sz = (gm < M) ? 8 : 0;
            asm volatile("cp.async.ca.shared.global [%0], [%1], 8, %2;\n"
                         :: "r"(sA + (uint32_t)((s * BM * BK + r * BK + cc * 2) * 4)),
                            "l"(src), "r"(sz));
        }
        for (int i = t; i < BK * D / 4; i += NT) {      // 500 16B chunks
            int rr = i / 50, cc = i - rr * 50;
            const float* src = Buse + (size_t)(k0 + rr) * D + cc * 4;
            asm volatile("cp.async.ca.shared.global [%0], [%1], 16;\n"
                         :: "r"(sB + (uint32_t)((s * BK * D + rr * D + cc * 4) * 4)),
                            "l"(src));
        }
        asm volatile("cp.async.commit_group;\n");
    };

    issue_tile(0);
    issue_tile(1);

    float2 acc0[25], acc1[25];
#pragma unroll
    for (int j = 0; j < 25; j++) {
        acc0[j] = make_float2(0.f, 0.f);
        acc1[j] = make_float2(0.f, 0.f);
    }

    for (int it = 0; it < NIT; it++) {
        asm volatile("cp.async.wait_group 1;\n");
        __syncthreads();
        const float* as = &As[it % NSTG][0];
        const float* bs = &Bs[it % NSTG][0];
        const int r0 = 2 * ty * BK, r1 = (2 * ty + 1) * BK;
#pragma unroll
        for (int kk = 0; kk < BK; kk += 2) {
            float2 a0 = *(const float2*)(as + r0 + kk);
            float2 a1 = *(const float2*)(as + r1 + kk);
            float2 a00 = make_float2(a0.x, a0.x), a01 = make_float2(a0.y, a0.y);
            float2 a10 = make_float2(a1.x, a1.x), a11 = make_float2(a1.y, a1.y);
            const float2* b0 = (const float2*)(bs + kk * D);
            const float2* b1 = (const float2*)(bs + (kk + 1) * D);
#pragma unroll
            for (int j = 0; j < 25; j++) {
                float2 bv0 = b0[tx + 4 * j];
                float2 bv1 = b1[tx + 4 * j];
                fma2(acc0[j], a00, bv0);
                fma2(acc1[j], a10, bv0);
                fma2(acc0[j], a01, bv1);
                fma2(acc1[j], a11, bv1);
            }
        }
        __syncthreads();
        if (it + 2 < NIT) issue_tile(it + 2);
        else asm volatile("cp.async.commit_group;\n");
    }

#pragma unroll
    for (int rr = 0; rr < 2; rr++) {
        int gm = m0 + 2 * ty + rr;
        if (gm >= M) continue;
        float2* accp = rr ? acc1 : acc0;
        if (MODE == 0) {
            float2* cp = (float2*)(C + (size_t)gm * D);
#pragma unroll
            for (int j = 0; j < 25; j++) cp[tx + 4 * j] = accp[j];
        } else if (MODE == 1) {
            int sI = ei[gm];
            int ev = et[gm];
            const float2* xr = (const float2*)(x + (size_t)sI * D);
            const float2* rv = (const float2*)(rel + (size_t)ev * D);
            float2* cp = (float2*)(C + (size_t)gm * D);
#pragma unroll
            for (int j = 0; j < 25; j++) {
                int c2 = tx + 4 * j;
                float2 q = accp[j], rl = rv[c2], xx = xr[c2];
                float2 o;
                o.x = xx.x * (0.5f * rl.x + 0.5f * q.x);
                o.y = xx.y * (0.5f * rl.y + 0.5f * q.y);
                cp[c2] = o;
            }
        } else {  // MODE 2 (in-place msg*norm)
            int e = ebase + gm;
            float nm = normArr[e];
            float2* cp = (float2*)(C + (size_t)e * D);
#pragma unroll
            for (int j = 0; j < 25; j++) {
                float2 q = accp[j];
                q.x *= nm; q.y *= nm;
                cp[tx + 4 * j] = q;
            }
        }
    }
}

// ---------------- CSR aggregate (loop + in + out) with fused BN stats ----------------
constexpr int AGG_BLOCKS = 400, ROWS_PB = NE / AGG_BLOCKS;  // 100 rows/block
__global__ void aggregate_k(const float* __restrict__ Pm, float* __restrict__ agg,
                            const int* __restrict__ off, const int* __restrict__ ce,
                            float* __restrict__ sum, float* __restrict__ sumsq) {
    int f2 = threadIdx.x;
    if (f2 >= D / 2) return;
    int r0 = blockIdx.x * ROWS_PB;
    float sx = 0.f, sy = 0.f, qx = 0.f, qy = 0.f;
    for (int r = r0; r < r0 + ROWS_PB; r++) {
        float2* ap = (float2*)(agg + (size_t)r * D);
        float2 v = ap[f2];
        int j0 = off[r], j1 = off[r + 1];
        for (int j = j0; j < j1; j++) {
            const float2* pr = (const float2*)(Pm + (size_t)ce[j] * D);
            float2 m = pr[f2];
            v.x += m.x;
            v.y += m.y;
        }
        ap[f2] = v;
        sx += v.x; sy += v.y;
        qx += v.x * v.x; qy += v.y * v.y;
    }
    atomicAdd(&sum[2 * f2], sx);
    atomicAdd(&sum[2 * f2 + 1], sy);
    atomicAdd(&sumsq[2 * f2], qx);
    atomicAdd(&sumsq[2 * f2 + 1], qy);
}

// ---------------- BN finalize + apply ----------------
__global__ void bn_final_k(const float* __restrict__ sum, const float* __restrict__ sumsq,
                           const float* __restrict__ gamma, const float* __restrict__ beta,
                           float* __restrict__ cA, float* __restrict__ cB) {
    int f = threadIdx.x;
    if (f >= D) return;
    float mean = sum[f] * (1.f / NE);
    float var  = sumsq[f] * (1.f / NE) - mean * mean;
    if (var < 0.f) var = 0.f;
    float rs = rsqrtf(var * (1.f / 9.f) + EPSV);
    float a  = gamma[f] * rs * (1.f / 3.f);
    cA[f] = a;
    cB[f] = beta[f] - a * mean;
}

__global__ void bn_apply_k(const float* __restrict__ t, const float* __restrict__ cA,
                           const float* __restrict__ cB, float* __restrict__ xo) {
    int i = blockIdx.x * blockDim.x + threadIdx.x;
    if (i < NE * D / 2) {
        int f2 = i % (D / 2);
        float2 v = ((const float2*)t)[i];
        float2 o;
        o.x = tanhf(cA[2 * f2] * v.x + cB[2 * f2]);
        o.y = tanhf(cA[2 * f2 + 1] * v.y + cB[2 * f2 + 1]);
        ((float2*)xo)[i] = o;
    }
}

// ---------------- output gathers ----------------
__global__ void gather_k(const float* __restrict__ src, const int* __restrict__ idx,
                         float* __restrict__ out) {
    int b = blockIdx.x;
    int f = threadIdx.x;
    if (f < D / 2) {
        ((float2*)(out + (size_t)b * D))[f] =
            ((const float2*)(src + (size_t)idx[b] * D))[f];
    }
}

// ---------------- driver ----------------
extern "C" void kernel_launch(void* const* d_in, const int* in_sizes, int n_in,
                              void* d_out, int out_size) {
    const int* ei  = (const int*)d_in[0];
    const int* et  = (const int*)d_in[1];
    const int* qe  = (const int*)d_in[2];
    const int* qr  = (const int*)d_in[3];
    const int* sub = (const int*)d_in[4];
    const int* rel = (const int*)d_in[5];
    const float* init_embed = (const float*)d_in[6];
    const float* init_rel   = (const float*)d_in[7];
    const float* L[2][9];
    for (int l = 0; l < 2; l++)
        for (int p = 0; p < 9; p++) L[l][p] = (const float*)d_in[8 + l * 9 + p];

    float *deg, *nrm, *relbuf, *r1, *r2, *W2, *Q, *P, *agg, *x1, *sum, *sumsq, *cA, *cB;
    int *cnt, *off, *cur, *ce;
    cudaGetSymbolAddress((void**)&deg,    g_deg);
    cudaGetSymbolAddress((void**)&nrm,    g_norm);
    cudaGetSymbolAddress((void**)&cnt,    g_cnt);
    cudaGetSymbolAddress((void**)&off,    g_off);
    cudaGetSymbolAddress((void**)&cur,    g_cur);
    cudaGetSymbolAddress((void**)&ce,     g_ce);
    cudaGetSymbolAddress((void**)&relbuf, g_relbuf);
    cudaGetSymbolAddress((void**)&r1,     g_r1);
    cudaGetSymbolAddress((void**)&r2,     g_r2);
    cudaGetSymbolAddress((void**)&W2,     g_W2);
    cudaGetSymbolAddress((void**)&Q,      g_Q);
    cudaGetSymbolAddress((void**)&P,      g_P);
    cudaGetSymbolAddress((void**)&agg,    g_agg);
    cudaGetSymbolAddress((void**)&x1,     g_x1);
    cudaGetSymbolAddress((void**)&sum,    g_sum);
    cudaGetSymbolAddress((void**)&sumsq,  g_sumsq);
    cudaGetSymbolAddress((void**)&cA,     g_cA);
    cudaGetSymbolAddress((void**)&cB,     g_cB);

    float* out     = (float*)d_out;
    float* out_sub = out;
    float* out_rel = out + NB * D;
    float* out_x   = out + 2 * NB * D;

    // degrees / norms / CSR (layer-invariant)
    cudaMemsetAsync(deg, 0, 2 * NE * sizeof(float));
    cudaMemsetAsync(cnt, 0, NE * sizeof(int));
    degcnt_k<<<(TOT + 255) / 256, 256>>>(ei, deg, cnt);
    norm_k<<<(TOT + 255) / 256, 256>>>(ei, deg, nrm);
    scan_k<<<1, SCAN_T>>>(cnt, off, cur);
    fill_k<<<(TOT + 255) / 256, 256>>>(ei, cur, ce);

    for (int l = 0; l < 2; l++) {
        const float* x_in = l ? x1 : init_embed;
        const float* r_in = l ? r1 : init_rel;
        float* x_out = l ? out_x : x1;
        float* r_out = l ? r2 : r1;

        cudaMemcpyAsync(relbuf, r_in, R2 * D * sizeof(float), cudaMemcpyDeviceToDevice);
        cudaMemcpyAsync(relbuf + R2 * D, L[l][5], D * sizeof(float), cudaMemcpyDeviceToDevice);
        cudaMemsetAsync(sum, 0, D * sizeof(float));
        cudaMemsetAsync(sumsq, 0, D * sizeof(float));

        prepw2_k<<<(D * D + 255) / 256, 256>>>(L[l][0], L[l][5], W2);
        build_q_k<<<TOT, 128>>>(x_in, relbuf, qe, qr, Q);
        // qual GEMM + fused P construction
        gemm_k<1><<<TOT / BM, NT>>>(Q, L[l][4], nullptr, P, TOT, ei, et, x_in,
                                    relbuf, nullptr);
        // msg GEMM: both halves, in-place P <- (P @ W) * norm
        gemm_k<2><<<2 * BLKS_HALF, NT>>>(P, L[l][1], L[l][2], P, EHALF, nullptr,
                                         nullptr, nullptr, nullptr, nrm);
        // self-loop GEMM: agg = x @ W2 (plain store)
        gemm_k<0><<<(NE + BM - 1) / BM, NT>>>((float*)x_in, W2, nullptr, agg, NE,
                                              nullptr, nullptr, nullptr, nullptr,
                                              nullptr);
        // CSR aggregate + fused BN stats
        aggregate_k<<<AGG_BLOCKS, 128>>>(P, agg, off, ce, sum, sumsq);
        bn_final_k<<<1, 224>>>(sum, sumsq, L[l][7], L[l][8], cA, cB);
        bn_apply_k<<<(NE * D / 2 + 255) / 256, 256>>>(agg, cA, cB, x_out);
        // rel update
        gemm_k<0><<<(R2 + BM - 1) / BM, NT>>>((float*)r_in, L[l][3], nullptr, r_out,
                                              R2, nullptr, nullptr, nullptr, nullptr,
                                              nullptr);
    }

    gather_k<<<NB, 128>>>(out_x, sub, out_sub);
    gather_k<<<NB, 128>>>(r2, rel, out_rel);
}